// round 1
// baseline (speedup 1.0000x reference)
#include <cuda_runtime.h>
#include <cstdint>

#define NT 1024
#define NH 2048
#define NI 2048
#define NEXP 16
#define NTOP 4
#define NSLOT (NT*NTOP)
#define NBLK 64            // 2048/32 scale blocks per row
#define ALPHA 1.702f
#define FLIMIT 7.0f

// ---------------- scratch (device globals: allocation-free) ----------------
__device__ int   g_tok_exp[NSLOT];
__device__ float g_tok_w[NSLOT];
__device__ int   g_counts[NEXP];
__device__ int   g_offsets[NEXP];
__device__ int   g_token_list[NSLOT];
__device__ int   g_slot_of[NSLOT];
__device__ float g_hbuf[(size_t)NSLOT * NI];   // 33.5 MB
__device__ float g_obuf[(size_t)NSLOT * NH];   // 33.5 MB

// ---------------- helpers ----------------
__device__ __forceinline__ float tf32r(float x){
    uint32_t r; asm("cvt.rna.tf32.f32 %0, %1;" : "=r"(r) : "f"(x));
    return __uint_as_float(r);
}

__device__ __forceinline__ void mma_tf32(float d[4], const uint32_t a[4], const uint32_t b[2]){
    asm volatile("mma.sync.aligned.m16n8k8.row.col.f32.tf32.tf32.f32 "
        "{%0,%1,%2,%3},{%4,%5,%6,%7},{%8,%9},{%0,%1,%2,%3};"
        : "+f"(d[0]),"+f"(d[1]),"+f"(d[2]),"+f"(d[3])
        : "r"(a[0]),"r"(a[1]),"r"(a[2]),"r"(a[3]),"r"(b[0]),"r"(b[1]));
}

__device__ __forceinline__ float act_fn(float g, float u){
    g = fminf(g, FLIMIT);
    u = fminf(fmaxf(u, -FLIMIT), FLIMIT);
    float sig = __fdividef(1.f, 1.f + __expf(-ALPHA*g));
    return (u + 1.f) * (g * sig);
}

template<int J>
__device__ __forceinline__ void sts_plain(float (*S)[36], int lrow, int kg, const float4* rv){
    #pragma unroll
    for (int j=0;j<J;j++){
        float4 v = rv[j];
        *(float4*)&S[lrow+32*j][kg*4] = make_float4(tf32r(v.x),tf32r(v.y),tf32r(v.z),tf32r(v.w));
    }
}
template<int J>
__device__ __forceinline__ void sts_scaled(float (*S)[36], int lrow, int kg, const float4* rv, const float* sc){
    #pragma unroll
    for (int j=0;j<J;j++){
        float4 v = rv[j]; float s = sc[j];
        *(float4*)&S[lrow+32*j][kg*4] = make_float4(tf32r(v.x*s),tf32r(v.y*s),tf32r(v.z*s),tf32r(v.w*s));
    }
}

// ---------------- K1: router ----------------
__global__ void router_kernel(const float* __restrict__ x,
                              const float* __restrict__ rw,
                              const float* __restrict__ rb)
{
    __shared__ float sx[NH];
    __shared__ float slog[NEXP];
    const int t = blockIdx.x;
    for (int i = threadIdx.x; i < NH; i += blockDim.x)
        sx[i] = x[(size_t)t*NH + i];
    __syncthreads();
    const int w = threadIdx.x >> 5;
    const int lane = threadIdx.x & 31;
    const float* wr = rw + (size_t)w*NH;
    float s = 0.f;
    for (int i = lane; i < NH; i += 32) s += sx[i]*wr[i];
    #pragma unroll
    for (int o=16;o>0;o>>=1) s += __shfl_xor_sync(0xffffffffu, s, o);
    if (lane==0) slog[w] = s + rb[w];
    __syncthreads();
    if (threadIdx.x==0){
        float v[NEXP];
        #pragma unroll
        for (int e=0;e<NEXP;e++) v[e]=slog[e];
        int idx[NTOP]; float val[NTOP];
        #pragma unroll
        for (int k=0;k<NTOP;k++){
            int bi=0; float bv=v[0];
            #pragma unroll
            for (int e=1;e<NEXP;e++){ if (v[e]>bv){bv=v[e];bi=e;} }
            idx[k]=bi; val[k]=bv; v[bi]=-3.4e38f;
        }
        float mx=val[0], ssum=0.f, ev[NTOP];
        #pragma unroll
        for(int k=0;k<NTOP;k++){ ev[k]=expf(val[k]-mx); ssum+=ev[k]; }
        float inv = 1.f/ssum;
        #pragma unroll
        for(int k=0;k<NTOP;k++){
            g_tok_exp[t*NTOP+k]=idx[k];
            g_tok_w[t*NTOP+k]=ev[k]*inv;
        }
    }
}

// ---------------- K2: build per-expert token lists ----------------
__global__ void build_lists_kernel()
{
    __shared__ int sc[NEXP], so[NEXP], scur[NEXP];
    const int t = threadIdx.x;         // 0..1023
    if (t < NEXP) sc[t]=0;
    __syncthreads();
    int ex[NTOP];
    #pragma unroll
    for (int k=0;k<NTOP;k++){ ex[k]=g_tok_exp[t*NTOP+k]; atomicAdd(&sc[ex[k]],1); }
    __syncthreads();
    if (t==0){
        int acc=0;
        for(int e=0;e<NEXP;e++){ so[e]=acc; acc+=sc[e]; }
    }
    __syncthreads();
    if (t<NEXP){ g_counts[t]=sc[t]; g_offsets[t]=so[t]; scur[t]=so[t]; }
    __syncthreads();
    #pragma unroll
    for (int k=0;k<NTOP;k++){
        int slot = atomicAdd(&scur[ex[k]],1);
        g_token_list[slot]=t;
        g_slot_of[t*NTOP+k]=slot;
    }
}

// ---------------- K3: fused gate+up GEMM + activation ----------------
// BM=128, BN=64 (per matrix), BK=32. 8 warps: warp grid 4(m)x2(n), warp tile 32x32.
__global__ void __launch_bounds__(256,1)
gateup_kernel(const float* __restrict__ x,
              const float* __restrict__ gblk, const float* __restrict__ gscl,
              const float* __restrict__ gbia,
              const float* __restrict__ ublk, const float* __restrict__ uscl,
              const float* __restrict__ ubia)
{
    __shared__ __align__(16) float As[128][36];
    __shared__ __align__(16) float Bg[64][36];
    __shared__ __align__(16) float Bu[64][36];
    __shared__ int sTok[128];

    const int e  = blockIdx.y >> 3;
    const int mt = blockIdx.y & 7;
    const int M  = g_counts[e];
    if (mt*128 >= M) return;
    const int off = g_offsets[e];
    const int n0  = blockIdx.x * 64;
    const int tid = threadIdx.x;

    if (tid < 128){
        int ml = mt*128 + tid; if (ml > M-1) ml = M-1;
        sTok[tid] = g_token_list[off + ml];
    }
    __syncthreads();

    const int lrow = tid >> 3;   // 0..31
    const int kg   = tid & 7;    // 0..7

    const float* xp[4];
    #pragma unroll
    for (int j=0;j<4;j++)
        xp[j] = x + (size_t)sTok[lrow+32*j]*NH + kg*4;
    const float* gp[2]; const float* up[2];
    const float* gsp[2]; const float* usp[2];
    #pragma unroll
    for (int j=0;j<2;j++){
        size_t r = (size_t)e*NI + (size_t)(n0 + lrow + 32*j);
        gp[j]  = gblk + r*NH + kg*4;
        up[j]  = ublk + r*NH + kg*4;
        gsp[j] = gscl + r*NBLK;
        usp[j] = uscl + r*NBLK;
    }

    float4 ra[4], rg[2], ru[2];
    float sg[2], su[2];

    // prologue: stage + commit chunk 0
    #pragma unroll
    for (int j=0;j<4;j++) ra[j] = *(const float4*)(xp[j]);
    #pragma unroll
    for (int j=0;j<2;j++){
        rg[j] = *(const float4*)(gp[j]);
        ru[j] = *(const float4*)(up[j]);
        sg[j] = gsp[j][0]; su[j] = usp[j][0];
    }
    sts_plain<4>(As, lrow, kg, ra);
    sts_scaled<2>(Bg, lrow, kg, rg, sg);
    sts_scaled<2>(Bu, lrow, kg, ru, su);
    __syncthreads();

    const int wid  = tid >> 5;
    const int lane = tid & 31;
    const int wm = (wid >> 1) * 32;
    const int wn = (wid & 1) * 32;
    const int fr = lane >> 2;
    const int fc = lane & 3;

    float accg[2][4][4];
    float accu[2][4][4];
    #pragma unroll
    for (int a=0;a<2;a++)
        #pragma unroll
        for(int b=0;b<4;b++)
            #pragma unroll
            for(int c=0;c<4;c++){ accg[a][b][c]=0.f; accu[a][b][c]=0.f; }

    for (int kc=0; kc<NH/32; kc++){
        const bool more = (kc+1 < NH/32);
        if (more){
            const int koff = (kc+1)*32;
            #pragma unroll
            for (int j=0;j<4;j++) ra[j] = *(const float4*)(xp[j] + koff);
            #pragma unroll
            for (int j=0;j<2;j++){
                rg[j] = *(const float4*)(gp[j] + koff);
                ru[j] = *(const float4*)(up[j] + koff);
                sg[j] = gsp[j][kc+1]; su[j] = usp[j][kc+1];
            }
        }
        #pragma unroll
        for (int ks=0; ks<4; ks++){
            const int kk = ks*8 + fc;
            uint32_t af[2][4];
            #pragma unroll
            for (int m2=0;m2<2;m2++){
                const int r = wm + m2*16 + fr;
                af[m2][0] = __float_as_uint(As[r  ][kk  ]);
                af[m2][1] = __float_as_uint(As[r+8][kk  ]);
                af[m2][2] = __float_as_uint(As[r  ][kk+4]);
                af[m2][3] = __float_as_uint(As[r+8][kk+4]);
            }
            #pragma unroll
            for (int nt=0; nt<4; nt++){
                const int c = wn + nt*8 + fr;
                uint32_t bg2[2] = {__float_as_uint(Bg[c][kk]), __float_as_uint(Bg[c][kk+4])};
                uint32_t bu2[2] = {__float_as_uint(Bu[c][kk]), __float_as_uint(Bu[c][kk+4])};
                #pragma unroll
                for (int m2=0;m2<2;m2++){
                    mma_tf32(accg[m2][nt], af[m2], bg2);
                    mma_tf32(accu[m2][nt], af[m2], bu2);
                }
            }
        }
        __syncthreads();
        if (more){
            sts_plain<4>(As, lrow, kg, ra);
            sts_scaled<2>(Bg, lrow, kg, rg, sg);
            sts_scaled<2>(Bu, lrow, kg, ru, su);
        }
        __syncthreads();
    }

    // epilogue: bias + clip + GLU, write h
    #pragma unroll
    for (int m2=0;m2<2;m2++){
        #pragma unroll
        for (int nt=0;nt<4;nt++){
            const int rl = mt*128 + wm + m2*16 + fr;
            const int cg = n0 + wn + nt*8 + fc*2;
            const float gb0 = gbia[(size_t)e*NI + cg];
            const float gb1 = gbia[(size_t)e*NI + cg + 1];
            const float ub0 = ubia[(size_t)e*NI + cg];
            const float ub1 = ubia[(size_t)e*NI + cg + 1];
            if (rl < M){
                float h0 = act_fn(accg[m2][nt][0]+gb0, accu[m2][nt][0]+ub0);
                float h1 = act_fn(accg[m2][nt][1]+gb1, accu[m2][nt][1]+ub1);
                *(float2*)&g_hbuf[(size_t)(off+rl)*NI + cg] = make_float2(h0,h1);
            }
            if (rl+8 < M){
                float h0 = act_fn(accg[m2][nt][2]+gb0, accu[m2][nt][2]+ub0);
                float h1 = act_fn(accg[m2][nt][3]+gb1, accu[m2][nt][3]+ub1);
                *(float2*)&g_hbuf[(size_t)(off+rl+8)*NI + cg] = make_float2(h0,h1);
            }
        }
    }
}

// ---------------- K4: down GEMM + bias ----------------
// BM=128, BN=128, BK=32. 8 warps: warp grid 2(m)x4(n), warp tile 64x32.
__global__ void __launch_bounds__(256,1)
down_kernel(const float* __restrict__ dblk, const float* __restrict__ dscl,
            const float* __restrict__ dbia)
{
    __shared__ __align__(16) float As[128][36];
    __shared__ __align__(16) float Bs[128][36];

    const int e  = blockIdx.y >> 3;
    const int mt = blockIdx.y & 7;
    const int M  = g_counts[e];
    if (mt*128 >= M) return;
    const int off = g_offsets[e];
    const int n0  = blockIdx.x * 128;
    const int tid = threadIdx.x;
    const int lrow = tid >> 3;
    const int kg   = tid & 7;

    const float* ap[4];
    const float* bp[4];
    const float* sp[4];
    #pragma unroll
    for (int j=0;j<4;j++){
        int ml = mt*128 + lrow + 32*j; if (ml > M-1) ml = M-1;
        ap[j] = g_hbuf + (size_t)(off+ml)*NI + kg*4;
        size_t r = (size_t)e*NH + (size_t)(n0 + lrow + 32*j);
        bp[j] = dblk + r*NI + kg*4;
        sp[j] = dscl + r*NBLK;
    }

    float4 ra[4], rb[4]; float sb[4];
    #pragma unroll
    for (int j=0;j<4;j++){
        ra[j] = *(const float4*)(ap[j]);
        rb[j] = *(const float4*)(bp[j]);
        sb[j] = sp[j][0];
    }
    sts_plain<4>(As, lrow, kg, ra);
    sts_scaled<4>(Bs, lrow, kg, rb, sb);
    __syncthreads();

    const int wid  = tid >> 5;
    const int lane = tid & 31;
    const int wm = (wid >> 2) * 64;
    const int wn = (wid & 3) * 32;
    const int fr = lane >> 2;
    const int fc = lane & 3;

    float acc[4][4][4];
    #pragma unroll
    for (int a=0;a<4;a++)
        #pragma unroll
        for(int b=0;b<4;b++)
            #pragma unroll
            for(int c=0;c<4;c++) acc[a][b][c]=0.f;

    for (int kc=0; kc<NI/32; kc++){
        const bool more = (kc+1 < NI/32);
        if (more){
            const int koff = (kc+1)*32;
            #pragma unroll
            for (int j=0;j<4;j++){
                ra[j] = *(const float4*)(ap[j] + koff);
                rb[j] = *(const float4*)(bp[j] + koff);
                sb[j] = sp[j][kc+1];
            }
        }
        #pragma unroll
        for (int ks=0; ks<4; ks++){
            const int kk = ks*8 + fc;
            uint32_t af[4][4];
            #pragma unroll
            for (int m2=0;m2<4;m2++){
                const int r = wm + m2*16 + fr;
                af[m2][0] = __float_as_uint(As[r  ][kk  ]);
                af[m2][1] = __float_as_uint(As[r+8][kk  ]);
                af[m2][2] = __float_as_uint(As[r  ][kk+4]);
                af[m2][3] = __float_as_uint(As[r+8][kk+4]);
            }
            #pragma unroll
            for (int nt=0; nt<4; nt++){
                const int c = wn + nt*8 + fr;
                uint32_t b2[2] = {__float_as_uint(Bs[c][kk]), __float_as_uint(Bs[c][kk+4])};
                #pragma unroll
                for (int m2=0;m2<4;m2++)
                    mma_tf32(acc[m2][nt], af[m2], b2);
            }
        }
        __syncthreads();
        if (more){
            sts_plain<4>(As, lrow, kg, ra);
            sts_scaled<4>(Bs, lrow, kg, rb, sb);
        }
        __syncthreads();
    }

    #pragma unroll
    for (int m2=0;m2<4;m2++){
        #pragma unroll
        for (int nt=0;nt<4;nt++){
            const int rl = mt*128 + wm + m2*16 + fr;
            const int cg = n0 + wn + nt*8 + fc*2;
            const float b0 = dbia[(size_t)e*NH + cg];
            const float b1 = dbia[(size_t)e*NH + cg + 1];
            if (rl < M){
                *(float2*)&g_obuf[(size_t)(off+rl)*NH + cg] =
                    make_float2(acc[m2][nt][0]+b0, acc[m2][nt][1]+b1);
            }
            if (rl+8 < M){
                *(float2*)&g_obuf[(size_t)(off+rl+8)*NH + cg] =
                    make_float2(acc[m2][nt][2]+b0, acc[m2][nt][3]+b1);
            }
        }
    }
}

// ---------------- K5: weighted combine ----------------
__global__ void combine_kernel(float* __restrict__ out)
{
    const int t = blockIdx.x;
    int sl[NTOP]; float w[NTOP];
    #pragma unroll
    for (int k=0;k<NTOP;k++){ sl[k]=g_slot_of[t*NTOP+k]; w[k]=g_tok_w[t*NTOP+k]; }
    for (int i = threadIdx.x; i < NH/4; i += blockDim.x){
        float4 a = make_float4(0.f,0.f,0.f,0.f);
        #pragma unroll
        for (int k=0;k<NTOP;k++){
            float4 v = *(const float4*)&g_obuf[(size_t)sl[k]*NH + i*4];
            a.x += w[k]*v.x; a.y += w[k]*v.y; a.z += w[k]*v.z; a.w += w[k]*v.w;
        }
        *(float4*)&out[(size_t)t*NH + i*4] = a;
    }
}

// ---------------- launch ----------------
extern "C" void kernel_launch(void* const* d_in, const int* in_sizes, int n_in,
                              void* d_out, int out_size)
{
    const float* x    = (const float*)d_in[0];
    const float* rw   = (const float*)d_in[1];
    const float* rb   = (const float*)d_in[2];
    const float* gblk = (const float*)d_in[3];
    const float* gscl = (const float*)d_in[4];
    const float* gbia = (const float*)d_in[5];
    const float* ublk = (const float*)d_in[6];
    const float* uscl = (const float*)d_in[7];
    const float* ubia = (const float*)d_in[8];
    const float* dblk = (const float*)d_in[9];
    const float* dscl = (const float*)d_in[10];
    const float* dbia = (const float*)d_in[11];
    float* out = (float*)d_out;

    router_kernel<<<NT, 512>>>(x, rw, rb);
    build_lists_kernel<<<1, NT>>>();
    gateup_kernel<<<dim3(NI/64, NEXP*8), 256>>>(x, gblk, gscl, gbia, ublk, uscl, ubia);
    down_kernel<<<dim3(NH/128, NEXP*8), 256>>>(dblk, dscl, dbia);
    combine_kernel<<<NT, 256>>>(out);
}